// round 13
// baseline (speedup 1.0000x reference)
#include <cuda_runtime.h>
#include <cstdint>

typedef unsigned long long ull;

// ---------- packed f32x2 helpers (sm_103a) ----------
__device__ __forceinline__ ull pack2(float a, float b) {
    ull r; asm("mov.b64 %0, {%1, %2};" : "=l"(r) : "f"(a), "f"(b)); return r;
}
__device__ __forceinline__ void unpack2(ull v, float& a, float& b) {
    asm("mov.b64 {%0, %1}, %2;" : "=f"(a), "=f"(b) : "l"(v));
}
__device__ __forceinline__ ull ffma2(ull a, ull b, ull c) {
    ull d; asm("fma.rn.f32x2 %0, %1, %2, %3;" : "=l"(d) : "l"(a), "l"(b), "l"(c)); return d;
}
__device__ __forceinline__ ull relu2(ull v) {
    float a, b; unpack2(v, a, b);
    return pack2(fmaxf(a, 0.f), fmaxf(b, 0.f));
}
#define DUP(f) pack2((f), (f))   // 1 ALU op: duplicate scalar weight into both halves

#define NJ 24
#define JWF 104         // floats per joint: 13 rows x 8 (7 weights + bias), NON-dup
#define WPB 17          // warps per block
#define TPAD 26         // sixth-tile row stride (26l mod 32 distinct per 16-lane phase; >=25)
#define TILE_FLOATS (64 * TPAD)                  // 6656 B
#define XS_ULL (24 * 32)                         // packed-x per warp: 6144 B
#define SW_BYTES (NJ * JWF * 4)                  // 9984
#define WARP_BYTES (XS_ULL * 8 + TILE_FLOATS * 4)          // 12800
#define SMEM_BYTES (SW_BYTES + WPB * WARP_BYTES)           // 227584 <= 232448

// ---- full joint: 7x7 layer1 + 6x7 layer2, non-dup weights (float4 view) ----
__device__ __forceinline__ void joint_fwd(const float4* wp, ull xp,
                                          const ull* pf, ull* fo) {
    ull h[7];
#pragma unroll
    for (int o = 0; o < 7; ++o) {
        float4 wa = wp[o * 2], wb = wp[o * 2 + 1];   // w0..w3 | w4,w5,w6,bias
        ull acc = ffma2(DUP(wa.x), xp, DUP(wb.w));
        acc = ffma2(DUP(wa.y), pf[0], acc);
        acc = ffma2(DUP(wa.z), pf[1], acc);
        acc = ffma2(DUP(wa.w), pf[2], acc);
        acc = ffma2(DUP(wb.x), pf[3], acc);
        acc = ffma2(DUP(wb.y), pf[4], acc);
        acc = ffma2(DUP(wb.z), pf[5], acc);
        h[o] = relu2(acc);
    }
#pragma unroll
    for (int o = 0; o < 6; ++o) {
        float4 wa = wp[14 + o * 2], wb = wp[14 + o * 2 + 1];
        ull acc = ffma2(DUP(wa.x), h[0], DUP(wb.w));
        acc = ffma2(DUP(wa.y), h[1], acc);
        acc = ffma2(DUP(wa.z), h[2], acc);
        acc = ffma2(DUP(wa.w), h[3], acc);
        acc = ffma2(DUP(wb.x), h[4], acc);
        acc = ffma2(DUP(wb.y), h[5], acc);
        acc = ffma2(DUP(wb.z), h[6], acc);
        fo[o] = relu2(acc);
    }
}

// root: parent features are zero
__device__ __forceinline__ void root_fwd(const float4* wp, ull xp, ull* fo) {
    ull h[7];
#pragma unroll
    for (int o = 0; o < 7; ++o) {
        float4 wa = wp[o * 2], wb = wp[o * 2 + 1];
        h[o] = relu2(ffma2(DUP(wa.x), xp, DUP(wb.w)));
    }
#pragma unroll
    for (int o = 0; o < 6; ++o) {
        float4 wa = wp[14 + o * 2], wb = wp[14 + o * 2 + 1];
        ull acc = ffma2(DUP(wa.x), h[0], DUP(wb.w));
        acc = ffma2(DUP(wa.y), h[1], acc);
        acc = ffma2(DUP(wa.z), h[2], acc);
        acc = ffma2(DUP(wa.w), h[3], acc);
        acc = ffma2(DUP(wb.x), h[4], acc);
        acc = ffma2(DUP(wb.y), h[5], acc);
        acc = ffma2(DUP(wb.z), h[6], acc);
        fo[o] = relu2(acc);
    }
}

// store 6 packed values: lows -> row ra, highs -> row rb (aligned float2)
__device__ __forceinline__ void store6(const ull* f, float* ra, float* rb, int cb) {
    float a0,b0,a1,b1,a2,b2,a3,b3,a4,b4,a5,b5;
    unpack2(f[0], a0, b0); unpack2(f[1], a1, b1); unpack2(f[2], a2, b2);
    unpack2(f[3], a3, b3); unpack2(f[4], a4, b4); unpack2(f[5], a5, b5);
    ((float2*)(ra + cb))[0] = make_float2(a0, a1);
    ((float2*)(ra + cb))[1] = make_float2(a2, a3);
    ((float2*)(ra + cb))[2] = make_float2(a4, a5);
    ((float2*)(rb + cb))[0] = make_float2(b0, b1);
    ((float2*)(rb + cb))[1] = make_float2(b2, b3);
    ((float2*)(rb + cb))[2] = make_float2(b4, b5);
}

__global__ void __launch_bounds__(WPB * 32)
StructureEncoder1D_kernel(const float* __restrict__ x,
                          const float* __restrict__ W1,
                          const float* __restrict__ b1,
                          const float* __restrict__ W2,
                          const float* __restrict__ b2,
                          float* __restrict__ out, int B) {
    extern __shared__ __align__(16) char dynsmem[];
    float* sw    = reinterpret_cast<float*>(dynsmem);                // non-dup weights
    char*  wbase = dynsmem + SW_BYTES;

    // ---- cooperative weight fill (plain floats, rows of 8) ----
    for (int i = threadIdx.x; i < NJ * JWF; i += blockDim.x) {
        int j = i / JWF, r = i % JWF, row = r >> 3, c = r & 7;
        float v;
        if (row < 7) {
            v = (c < 7) ? W1[j * 49 + row * 7 + c] : b1[j * 7 + row];
        } else {
            int rr = row - 7;
            v = (c < 7) ? W2[j * 42 + rr * 7 + c] : b2[j * 6 + rr];
        }
        sw[i] = v;
    }
    __syncthreads();

    const int lane   = threadIdx.x & 31;
    const int warpId = threadIdx.x >> 5;
    const int warpBase = (blockIdx.x * WPB + warpId) * 64;
    if (warpBase >= B) return;

    char* wb = wbase + warpId * WARP_BYTES;
    ull*   xs   = reinterpret_cast<ull*>(wb);
    float* tile = reinterpret_cast<float*>(wb + XS_ULL * 8);

    // ---- stage x: coalesced LDG.128 -> tile region (row stride 25 floats) ----
    {
        const float4* xin = reinterpret_cast<const float4*>(x);
#pragma unroll
        for (int k = 0; k < 12; ++k) {
            int i = k * 32 + lane;               // [0,384): 64 rows x 6 float4
            int r = i / 6, c = i % 6;
            float4 v = make_float4(0.f, 0.f, 0.f, 0.f);
            if (warpBase + r < B) v = xin[(size_t)(warpBase + r) * 6 + c];
            float* d = tile + r * 25 + c * 4;
            d[0] = v.x; d[1] = v.y; d[2] = v.z; d[3] = v.w;
        }
    }
    __syncwarp();

    // ---- build packed-x in xs: xs[j*32+lane] = {x[e0][j], x[e1][j]} ----
#pragma unroll
    for (int j = 0; j < 24; ++j) {
        float a = tile[lane * 25 + j];
        float b = tile[(lane + 32) * 25 + j];
        xs[j * 32 + lane] = pack2(a, b);
    }
    __syncwarp();

    float* ta = tile + lane * TPAD;          // even offset -> aligned float2
    float* tb = tile + (lane + 32) * TPAD;

    ull fA[6], fB[6], fC[6];

#define XP(J) (xs[(J) * 32 + lane])
#define WP(J) (reinterpret_cast<const float4*>(sw) + (J) * 26)
#define ST(F, CB) store6(F, ta, tb, CB)

    // flush sixth tile: 64 rows x 24 cols -> out cols [G*24, G*24+24)
#define FLUSH(G) do {                                                          \
        __syncwarp();                                                          \
        _Pragma("unroll")                                                      \
        for (int k = 0; k < 12; ++k) {                                         \
            int i = k * 32 + lane;               /* [0,384): 64 rows x 6 f4 */ \
            int r = i / 6, c = i % 6;                                          \
            if (warpBase + r < B) {                                            \
                const float2* s = reinterpret_cast<const float2*>(             \
                    tile + r * TPAD + c * 4);                                  \
                float2 lo = s[0], hi = s[1];                                   \
                *reinterpret_cast<float4*>(                                    \
                    out + (size_t)(warpBase + r) * 144 + (G) * 24 + c * 4) =   \
                    make_float4(lo.x, lo.y, hi.x, hi.y);                       \
            }                                                                  \
        }                                                                      \
        __syncwarp();                                                          \
    } while (0)

    // ---- phase 0: joints {0,1,2,3}, local col = j*6 ----
    root_fwd (WP(0), XP(0),      fA);  ST(fA, 0);    // fA = f0
    joint_fwd(WP(1), XP(1), fA,  fB);  ST(fB, 6);    // fB = f1
    joint_fwd(WP(2), XP(2), fA,  fC);  ST(fC, 12);   // fC = f2
    joint_fwd(WP(3), XP(3), fA,  fA);  ST(fA, 18);   // fA = f3  (f0 dead)
    FLUSH(0);

    // ---- phase 1: {4,5,6,7}  (fB=f1, fC=f2, fA=f3) ----
    joint_fwd(WP(4), XP(4), fB,  fB);  ST(fB, 0);    // fB = f4
    joint_fwd(WP(7), XP(7), fB,  fB);  ST(fB, 18);   // fB = f7  (f4 child: 7 only)
    joint_fwd(WP(5), XP(5), fC,  fC);  ST(fC, 6);    // fC = f5
    joint_fwd(WP(6), XP(6), fA,  fA);  ST(fA, 12);   // fA = f6
    FLUSH(1);

    // ---- phase 2: {8,9,10,11}  (fC=f5, fA=f6, fB=f7) ----
    joint_fwd(WP(8),  XP(8),  fC, fC); ST(fC, 0);    // fC = f8
    joint_fwd(WP(11), XP(11), fC, fC); ST(fC, 18);   // f11 leaf (f8 child: 11 only)
    joint_fwd(WP(9),  XP(9),  fA, fA); ST(fA, 6);    // fA = f9
    joint_fwd(WP(10), XP(10), fB, fB); ST(fB, 12);   // f10 leaf
    FLUSH(2);

    // ---- phase 3: {12,13,14,15}  (fA=f9; 12,13,14 <- 9) ----
    joint_fwd(WP(12), XP(12), fA, fB); ST(fB, 0);    // fB = f12
    joint_fwd(WP(15), XP(15), fB, fB); ST(fB, 18);   // f15 leaf (f12 child: 15 only)
    joint_fwd(WP(13), XP(13), fA, fC); ST(fC, 6);    // fC = f13
    joint_fwd(WP(14), XP(14), fA, fA); ST(fA, 12);   // fA = f14 (f9 dead)
    FLUSH(3);

    // ---- phase 4: {16,17,18,19}  (fC=f13, fA=f14) ----
    joint_fwd(WP(16), XP(16), fC, fC); ST(fC, 0);    // fC = f16
    joint_fwd(WP(18), XP(18), fC, fC); ST(fC, 12);   // fC = f18 (f16 child: 18 only)
    joint_fwd(WP(17), XP(17), fA, fA); ST(fA, 6);    // fA = f17
    joint_fwd(WP(19), XP(19), fA, fA); ST(fA, 18);   // fA = f19 (f17 child: 19 only)
    FLUSH(4);

    // ---- phase 5: {20,21,22,23}  (fC=f18, fA=f19) ----
    joint_fwd(WP(20), XP(20), fC, fC); ST(fC, 0);    // fC = f20
    joint_fwd(WP(22), XP(22), fC, fC); ST(fC, 12);   // f22 leaf
    joint_fwd(WP(21), XP(21), fA, fA); ST(fA, 6);    // fA = f21
    joint_fwd(WP(23), XP(23), fA, fA); ST(fA, 18);   // f23 leaf
    FLUSH(5);

#undef XP
#undef WP
#undef ST
#undef FLUSH
}

extern "C" void kernel_launch(void* const* d_in, const int* in_sizes, int n_in,
                              void* d_out, int out_size) {
    const float* x  = (const float*)d_in[0];
    const float* W1 = (const float*)d_in[1];
    const float* b1 = (const float*)d_in[2];
    const float* W2 = (const float*)d_in[3];
    const float* b2 = (const float*)d_in[4];
    float* out = (float*)d_out;

    int B = in_sizes[0] / 24;
    int warps  = (B + 63) / 64;
    int blocks = (warps + WPB - 1) / WPB;

    cudaFuncSetAttribute(StructureEncoder1D_kernel,
                         cudaFuncAttributeMaxDynamicSharedMemorySize, SMEM_BYTES);
    StructureEncoder1D_kernel<<<blocks, WPB * 32, SMEM_BYTES>>>(x, W1, b1, W2, b2, out, B);
}

// round 14
// speedup vs baseline: 1.7706x; 1.7706x over previous
#include <cuda_runtime.h>
#include <cstdint>

typedef unsigned long long ull;

// ---------- packed f32x2 helpers (sm_103a) ----------
__device__ __forceinline__ ull pack2(float a, float b) {
    ull r; asm("mov.b64 %0, {%1, %2};" : "=l"(r) : "f"(a), "f"(b)); return r;
}
__device__ __forceinline__ void unpack2(ull v, float& a, float& b) {
    asm("mov.b64 {%0, %1}, %2;" : "=f"(a), "=f"(b) : "l"(v));
}
__device__ __forceinline__ ull ffma2(ull a, ull b, ull c) {
    ull d; asm("fma.rn.f32x2 %0, %1, %2, %3;" : "=l"(d) : "l"(a), "l"(b), "l"(c)); return d;
}
__device__ __forceinline__ ull relu2(ull v) {
    float a, b; unpack2(v, a, b);
    return pack2(fmaxf(a, 0.f), fmaxf(b, 0.f));
}
#define DUP(f) pack2((f), (f))   // 1 ALU op: duplicate scalar weight into both halves

#define NJ 24
#define JWF 104         // floats per joint: 13 rows x 8 (7 weights + bias), NON-dup
#define WPB 16          // warps per block (512 thr -> reg cap 128 = R12's usage)
#define TPAD 26         // sixth-tile row stride (26l mod 32 distinct per 16-lane phase; >=25)
#define TILE_FLOATS (64 * TPAD)                  // 6656 B
#define XS_ULL (24 * 32)                         // packed-x per warp: 6144 B
#define SW_BYTES (NJ * JWF * 4)                  // 9984
#define WARP_BYTES (XS_ULL * 8 + TILE_FLOATS * 4)          // 12800
#define SMEM_BYTES (SW_BYTES + WPB * WARP_BYTES)           // 214784 <= 232448

// ---- full joint: 7x7 layer1 + 6x7 layer2, non-dup weights (float4 view) ----
__device__ __forceinline__ void joint_fwd(const float4* wp, ull xp,
                                          const ull* pf, ull* fo) {
    ull h[7];
#pragma unroll
    for (int o = 0; o < 7; ++o) {
        float4 wa = wp[o * 2], wb = wp[o * 2 + 1];   // w0..w3 | w4,w5,w6,bias
        ull acc = ffma2(DUP(wa.x), xp, DUP(wb.w));
        acc = ffma2(DUP(wa.y), pf[0], acc);
        acc = ffma2(DUP(wa.z), pf[1], acc);
        acc = ffma2(DUP(wa.w), pf[2], acc);
        acc = ffma2(DUP(wb.x), pf[3], acc);
        acc = ffma2(DUP(wb.y), pf[4], acc);
        acc = ffma2(DUP(wb.z), pf[5], acc);
        h[o] = relu2(acc);
    }
#pragma unroll
    for (int o = 0; o < 6; ++o) {
        float4 wa = wp[14 + o * 2], wb = wp[14 + o * 2 + 1];
        ull acc = ffma2(DUP(wa.x), h[0], DUP(wb.w));
        acc = ffma2(DUP(wa.y), h[1], acc);
        acc = ffma2(DUP(wa.z), h[2], acc);
        acc = ffma2(DUP(wa.w), h[3], acc);
        acc = ffma2(DUP(wb.x), h[4], acc);
        acc = ffma2(DUP(wb.y), h[5], acc);
        acc = ffma2(DUP(wb.z), h[6], acc);
        fo[o] = relu2(acc);
    }
}

// root: parent features are zero
__device__ __forceinline__ void root_fwd(const float4* wp, ull xp, ull* fo) {
    ull h[7];
#pragma unroll
    for (int o = 0; o < 7; ++o) {
        float4 wa = wp[o * 2], wb = wp[o * 2 + 1];
        h[o] = relu2(ffma2(DUP(wa.x), xp, DUP(wb.w)));
    }
#pragma unroll
    for (int o = 0; o < 6; ++o) {
        float4 wa = wp[14 + o * 2], wb = wp[14 + o * 2 + 1];
        ull acc = ffma2(DUP(wa.x), h[0], DUP(wb.w));
        acc = ffma2(DUP(wa.y), h[1], acc);
        acc = ffma2(DUP(wa.z), h[2], acc);
        acc = ffma2(DUP(wa.w), h[3], acc);
        acc = ffma2(DUP(wb.x), h[4], acc);
        acc = ffma2(DUP(wb.y), h[5], acc);
        acc = ffma2(DUP(wb.z), h[6], acc);
        fo[o] = relu2(acc);
    }
}

// store 6 packed values: lows -> row ra, highs -> row rb (aligned float2)
__device__ __forceinline__ void store6(const ull* f, float* ra, float* rb, int cb) {
    float a0,b0,a1,b1,a2,b2,a3,b3,a4,b4,a5,b5;
    unpack2(f[0], a0, b0); unpack2(f[1], a1, b1); unpack2(f[2], a2, b2);
    unpack2(f[3], a3, b3); unpack2(f[4], a4, b4); unpack2(f[5], a5, b5);
    ((float2*)(ra + cb))[0] = make_float2(a0, a1);
    ((float2*)(ra + cb))[1] = make_float2(a2, a3);
    ((float2*)(ra + cb))[2] = make_float2(a4, a5);
    ((float2*)(rb + cb))[0] = make_float2(b0, b1);
    ((float2*)(rb + cb))[1] = make_float2(b2, b3);
    ((float2*)(rb + cb))[2] = make_float2(b4, b5);
}

__global__ void __launch_bounds__(WPB * 32)
StructureEncoder1D_kernel(const float* __restrict__ x,
                          const float* __restrict__ W1,
                          const float* __restrict__ b1,
                          const float* __restrict__ W2,
                          const float* __restrict__ b2,
                          float* __restrict__ out, int B) {
    extern __shared__ __align__(16) char dynsmem[];
    float* sw    = reinterpret_cast<float*>(dynsmem);                // non-dup weights
    char*  wbase = dynsmem + SW_BYTES;

    // ---- cooperative weight fill (plain floats, rows of 8) ----
    for (int i = threadIdx.x; i < NJ * JWF; i += blockDim.x) {
        int j = i / JWF, r = i % JWF, row = r >> 3, c = r & 7;
        float v;
        if (row < 7) {
            v = (c < 7) ? W1[j * 49 + row * 7 + c] : b1[j * 7 + row];
        } else {
            int rr = row - 7;
            v = (c < 7) ? W2[j * 42 + rr * 7 + c] : b2[j * 6 + rr];
        }
        sw[i] = v;
    }
    __syncthreads();

    const int lane   = threadIdx.x & 31;
    const int warpId = threadIdx.x >> 5;
    const int warpBase = (blockIdx.x * WPB + warpId) * 64;
    if (warpBase >= B) return;

    char* wb = wbase + warpId * WARP_BYTES;
    ull*   xs   = reinterpret_cast<ull*>(wb);
    float* tile = reinterpret_cast<float*>(wb + XS_ULL * 8);

    // ---- stage x: coalesced LDG.128 -> tile region (row stride 25 floats) ----
    {
        const float4* xin = reinterpret_cast<const float4*>(x);
#pragma unroll
        for (int k = 0; k < 12; ++k) {
            int i = k * 32 + lane;               // [0,384): 64 rows x 6 float4
            int r = i / 6, c = i % 6;
            float4 v = make_float4(0.f, 0.f, 0.f, 0.f);
            if (warpBase + r < B) v = xin[(size_t)(warpBase + r) * 6 + c];
            float* d = tile + r * 25 + c * 4;
            d[0] = v.x; d[1] = v.y; d[2] = v.z; d[3] = v.w;
        }
    }
    __syncwarp();

    // ---- build packed-x in xs: xs[j*32+lane] = {x[e0][j], x[e1][j]} ----
#pragma unroll
    for (int j = 0; j < 24; ++j) {
        float a = tile[lane * 25 + j];
        float b = tile[(lane + 32) * 25 + j];
        xs[j * 32 + lane] = pack2(a, b);
    }
    __syncwarp();

    float* ta = tile + lane * TPAD;          // even offset -> aligned float2
    float* tb = tile + (lane + 32) * TPAD;

    ull fA[6], fB[6], fC[6];

#define XP(J) (xs[(J) * 32 + lane])
#define WP(J) (reinterpret_cast<const float4*>(sw) + (J) * 26)
#define ST(F, CB) store6(F, ta, tb, CB)

    // flush sixth tile: 64 rows x 24 cols -> out cols [G*24, G*24+24)
#define FLUSH(G) do {                                                          \
        __syncwarp();                                                          \
        _Pragma("unroll")                                                      \
        for (int k = 0; k < 12; ++k) {                                         \
            int i = k * 32 + lane;               /* [0,384): 64 rows x 6 f4 */ \
            int r = i / 6, c = i % 6;                                          \
            if (warpBase + r < B) {                                            \
                const float2* s = reinterpret_cast<const float2*>(             \
                    tile + r * TPAD + c * 4);                                  \
                float2 lo = s[0], hi = s[1];                                   \
                *reinterpret_cast<float4*>(                                    \
                    out + (size_t)(warpBase + r) * 144 + (G) * 24 + c * 4) =   \
                    make_float4(lo.x, lo.y, hi.x, hi.y);                       \
            }                                                                  \
        }                                                                      \
        __syncwarp();                                                          \
    } while (0)

    // ---- phase 0: joints {0,1,2,3}, local col = j*6 ----
    root_fwd (WP(0), XP(0),      fA);  ST(fA, 0);    // fA = f0
    joint_fwd(WP(1), XP(1), fA,  fB);  ST(fB, 6);    // fB = f1
    joint_fwd(WP(2), XP(2), fA,  fC);  ST(fC, 12);   // fC = f2
    joint_fwd(WP(3), XP(3), fA,  fA);  ST(fA, 18);   // fA = f3  (f0 dead)
    FLUSH(0);

    // ---- phase 1: {4,5,6,7}  (fB=f1, fC=f2, fA=f3) ----
    joint_fwd(WP(4), XP(4), fB,  fB);  ST(fB, 0);    // fB = f4
    joint_fwd(WP(7), XP(7), fB,  fB);  ST(fB, 18);   // fB = f7  (f4 child: 7 only)
    joint_fwd(WP(5), XP(5), fC,  fC);  ST(fC, 6);    // fC = f5
    joint_fwd(WP(6), XP(6), fA,  fA);  ST(fA, 12);   // fA = f6
    FLUSH(1);

    // ---- phase 2: {8,9,10,11}  (fC=f5, fA=f6, fB=f7) ----
    joint_fwd(WP(8),  XP(8),  fC, fC); ST(fC, 0);    // fC = f8
    joint_fwd(WP(11), XP(11), fC, fC); ST(fC, 18);   // f11 leaf (f8 child: 11 only)
    joint_fwd(WP(9),  XP(9),  fA, fA); ST(fA, 6);    // fA = f9
    joint_fwd(WP(10), XP(10), fB, fB); ST(fB, 12);   // f10 leaf
    FLUSH(2);

    // ---- phase 3: {12,13,14,15}  (fA=f9; 12,13,14 <- 9) ----
    joint_fwd(WP(12), XP(12), fA, fB); ST(fB, 0);    // fB = f12
    joint_fwd(WP(15), XP(15), fB, fB); ST(fB, 18);   // f15 leaf (f12 child: 15 only)
    joint_fwd(WP(13), XP(13), fA, fC); ST(fC, 6);    // fC = f13
    joint_fwd(WP(14), XP(14), fA, fA); ST(fA, 12);   // fA = f14 (f9 dead)
    FLUSH(3);

    // ---- phase 4: {16,17,18,19}  (fC=f13, fA=f14) ----
    joint_fwd(WP(16), XP(16), fC, fC); ST(fC, 0);    // fC = f16
    joint_fwd(WP(18), XP(18), fC, fC); ST(fC, 12);   // fC = f18 (f16 child: 18 only)
    joint_fwd(WP(17), XP(17), fA, fA); ST(fA, 6);    // fA = f17
    joint_fwd(WP(19), XP(19), fA, fA); ST(fA, 18);   // fA = f19 (f17 child: 19 only)
    FLUSH(4);

    // ---- phase 5: {20,21,22,23}  (fC=f18, fA=f19) ----
    joint_fwd(WP(20), XP(20), fC, fC); ST(fC, 0);    // fC = f20
    joint_fwd(WP(22), XP(22), fC, fC); ST(fC, 12);   // f22 leaf
    joint_fwd(WP(21), XP(21), fA, fA); ST(fA, 6);    // fA = f21
    joint_fwd(WP(23), XP(23), fA, fA); ST(fA, 18);   // f23 leaf
    FLUSH(5);

#undef XP
#undef WP
#undef ST
#undef FLUSH
}

extern "C" void kernel_launch(void* const* d_in, const int* in_sizes, int n_in,
                              void* d_out, int out_size) {
    const float* x  = (const float*)d_in[0];
    const float* W1 = (const float*)d_in[1];
    const float* b1 = (const float*)d_in[2];
    const float* W2 = (const float*)d_in[3];
    const float* b2 = (const float*)d_in[4];
    float* out = (float*)d_out;

    int B = in_sizes[0] / 24;
    int warps  = (B + 63) / 64;
    int blocks = (warps + WPB - 1) / WPB;

    cudaFuncSetAttribute(StructureEncoder1D_kernel,
                         cudaFuncAttributeMaxDynamicSharedMemorySize, SMEM_BYTES);
    StructureEncoder1D_kernel<<<blocks, WPB * 32, SMEM_BYTES>>>(x, W1, b1, W2, b2, out, B);
}

// round 15
// speedup vs baseline: 1.9497x; 1.1012x over previous
#include <cuda_runtime.h>
#include <cstdint>

typedef unsigned long long ull;

// ---------- packed f32x2 helpers (sm_103a) ----------
__device__ __forceinline__ ull pack2(float a, float b) {
    ull r; asm("mov.b64 %0, {%1, %2};" : "=l"(r) : "f"(a), "f"(b)); return r;
}
__device__ __forceinline__ void unpack2(ull v, float& a, float& b) {
    asm("mov.b64 {%0, %1}, %2;" : "=f"(a), "=f"(b) : "l"(v));
}
__device__ __forceinline__ ull ffma2(ull a, ull b, ull c) {
    ull d; asm("fma.rn.f32x2 %0, %1, %2, %3;" : "=l"(d) : "l"(a), "l"(b), "l"(c)); return d;
}
__device__ __forceinline__ ull relu2(ull v) {
    float a, b; unpack2(v, a, b);
    return pack2(fmaxf(a, 0.f), fmaxf(b, 0.f));
}
#define DUP(f) pack2((f), (f))

#define NJ 24
#define JWU 64          // ull per joint (col-major output-pair layout, padded)
#define WPB 14          // warps per block (448 thr -> reg cap 146)
#define TPAD 36         // quarter-tile row stride (18l mod 32 distinct per 16-lane phase)
#define TILE_FLOATS (64 * TPAD)                  // 9216 B
#define XS_ULL (24 * 32)                         // packed-x per warp: 6144 B
#define SW_BYTES (NJ * JWU * 8)                  // 12288
#define WARP_BYTES (XS_ULL * 8 + TILE_FLOATS * 4)          // 15360
#define SMEM_BYTES (SW_BYTES + WPB * WARP_BYTES)           // 227328 <= 232448

// Weight image per joint (ull index s in [0,64)):
//  s in [0,28):  layer1 W-pairs: s = k*4+p, pair = (W1[2p][k], W1[2p+1][k]); p=3 -> (W1[6][k], 0)
//  s in [28,32): layer1 bias pairs: (b1[2p], b1[2p+1]); p=3 -> (b1[6], 0)
//  s in [32,60): layer2 W-pairs: s-32 = k*4+p (p<3), pair = (W2[2p][k], W2[2p+1][k]); p=3 pad 0
//  s in [60,63): layer2 bias pairs: (b2[2p], b2[2p+1])
//  s = 63: pad

// ---- joint forward: both batch elements (A=lo, B=hi of xp/feature packs) share weight regs.
// pf[0..2] = elem-A feature trio (f0,f1)(f2,f3)(f4,f5), pf[3..5] = elem-B trio. fo same layout.
__device__ __forceinline__ void joint_fwd(const ull* jw, ull xp,
                                          const ull* pf, ull* fo) {
    // duplicate scalar inputs
    float xa, xb; unpack2(xp, xa, xb);
    ull dA[7], dB[7];
    dA[0] = DUP(xa); dB[0] = DUP(xb);
#pragma unroll
    for (int s = 0; s < 3; ++s) {
        float a, b, c, d;
        unpack2(pf[s],     a, b);
        unpack2(pf[3 + s], c, d);
        dA[1 + 2*s] = DUP(a); dA[2 + 2*s] = DUP(b);
        dB[1 + 2*s] = DUP(c); dB[2 + 2*s] = DUP(d);
    }
    const ulonglong2* W = reinterpret_cast<const ulonglong2*>(jw);
    ulonglong2 b01 = W[14], b23 = W[15];
    ull aA0 = b01.x, aA1 = b01.y, aA2 = b23.x, aA3 = b23.y;
    ull aB0 = b01.x, aB1 = b01.y, aB2 = b23.x, aB3 = b23.y;
#pragma unroll
    for (int k = 0; k < 7; ++k) {
        ulonglong2 w01 = W[k * 2], w23 = W[k * 2 + 1];
        aA0 = ffma2(w01.x, dA[k], aA0);  aB0 = ffma2(w01.x, dB[k], aB0);
        aA1 = ffma2(w01.y, dA[k], aA1);  aB1 = ffma2(w01.y, dB[k], aB1);
        aA2 = ffma2(w23.x, dA[k], aA2);  aB2 = ffma2(w23.x, dB[k], aB2);
        aA3 = ffma2(w23.y, dA[k], aA3);  aB3 = ffma2(w23.y, dB[k], aB3);
    }
    aA0 = relu2(aA0); aA1 = relu2(aA1); aA2 = relu2(aA2); aA3 = relu2(aA3);
    aB0 = relu2(aB0); aB1 = relu2(aB1); aB2 = relu2(aB2); aB3 = relu2(aB3);

    // duplicate hidden scalars (h7 pad ignored)
    ull eA[7], eB[7];
    {
        float a, b;
        unpack2(aA0, a, b); eA[0] = DUP(a); eA[1] = DUP(b);
        unpack2(aA1, a, b); eA[2] = DUP(a); eA[3] = DUP(b);
        unpack2(aA2, a, b); eA[4] = DUP(a); eA[5] = DUP(b);
        unpack2(aA3, a, b); eA[6] = DUP(a);
        unpack2(aB0, a, b); eB[0] = DUP(a); eB[1] = DUP(b);
        unpack2(aB1, a, b); eB[2] = DUP(a); eB[3] = DUP(b);
        unpack2(aB2, a, b); eB[4] = DUP(a); eB[5] = DUP(b);
        unpack2(aB3, a, b); eB[6] = DUP(a);
    }
    ulonglong2 c01 = *reinterpret_cast<const ulonglong2*>(jw + 60);
    ull c2 = jw[62];
    ull gA0 = c01.x, gA1 = c01.y, gA2 = c2;
    ull gB0 = c01.x, gB1 = c01.y, gB2 = c2;
#pragma unroll
    for (int k = 0; k < 7; ++k) {
        const ulonglong2* L = reinterpret_cast<const ulonglong2*>(jw + 32 + k * 4);
        ulonglong2 w01 = L[0], w2p = L[1];
        gA0 = ffma2(w01.x, eA[k], gA0);  gB0 = ffma2(w01.x, eB[k], gB0);
        gA1 = ffma2(w01.y, eA[k], gA1);  gB1 = ffma2(w01.y, eB[k], gB1);
        gA2 = ffma2(w2p.x, eA[k], gA2);  gB2 = ffma2(w2p.x, eB[k], gB2);
    }
    fo[0] = relu2(gA0); fo[1] = relu2(gA1); fo[2] = relu2(gA2);
    fo[3] = relu2(gB0); fo[4] = relu2(gB1); fo[5] = relu2(gB2);
}

// root: parent features are zero -> layer1 keeps only the x term + bias
__device__ __forceinline__ void root_fwd(const ull* jw, ull xp, ull* fo) {
    float xa, xb; unpack2(xp, xa, xb);
    ull dA = DUP(xa), dB = DUP(xb);
    const ulonglong2* W = reinterpret_cast<const ulonglong2*>(jw);
    ulonglong2 w01 = W[0], w23 = W[1], b01 = W[14], b23 = W[15];
    ull aA0 = ffma2(w01.x, dA, b01.x), aB0 = ffma2(w01.x, dB, b01.x);
    ull aA1 = ffma2(w01.y, dA, b01.y), aB1 = ffma2(w01.y, dB, b01.y);
    ull aA2 = ffma2(w23.x, dA, b23.x), aB2 = ffma2(w23.x, dB, b23.x);
    ull aA3 = ffma2(w23.y, dA, b23.y), aB3 = ffma2(w23.y, dB, b23.y);
    aA0 = relu2(aA0); aA1 = relu2(aA1); aA2 = relu2(aA2); aA3 = relu2(aA3);
    aB0 = relu2(aB0); aB1 = relu2(aB1); aB2 = relu2(aB2); aB3 = relu2(aB3);

    ull eA[7], eB[7];
    {
        float a, b;
        unpack2(aA0, a, b); eA[0] = DUP(a); eA[1] = DUP(b);
        unpack2(aA1, a, b); eA[2] = DUP(a); eA[3] = DUP(b);
        unpack2(aA2, a, b); eA[4] = DUP(a); eA[5] = DUP(b);
        unpack2(aA3, a, b); eA[6] = DUP(a);
        unpack2(aB0, a, b); eB[0] = DUP(a); eB[1] = DUP(b);
        unpack2(aB1, a, b); eB[2] = DUP(a); eB[3] = DUP(b);
        unpack2(aB2, a, b); eB[4] = DUP(a); eB[5] = DUP(b);
        unpack2(aB3, a, b); eB[6] = DUP(a);
    }
    ulonglong2 c01 = *reinterpret_cast<const ulonglong2*>(jw + 60);
    ull c2 = jw[62];
    ull gA0 = c01.x, gA1 = c01.y, gA2 = c2;
    ull gB0 = c01.x, gB1 = c01.y, gB2 = c2;
#pragma unroll
    for (int k = 0; k < 7; ++k) {
        const ulonglong2* L = reinterpret_cast<const ulonglong2*>(jw + 32 + k * 4);
        ulonglong2 w01 = L[0], w2p = L[1];
        gA0 = ffma2(w01.x, eA[k], gA0);  gB0 = ffma2(w01.x, eB[k], gB0);
        gA1 = ffma2(w01.y, eA[k], gA1);  gB1 = ffma2(w01.y, eB[k], gB1);
        gA2 = ffma2(w2p.x, eA[k], gA2);  gB2 = ffma2(w2p.x, eB[k], gB2);
    }
    fo[0] = relu2(gA0); fo[1] = relu2(gA1); fo[2] = relu2(gA2);
    fo[3] = relu2(gB0); fo[4] = relu2(gB1); fo[5] = relu2(gB2);
}

__global__ void __launch_bounds__(WPB * 32)
StructureEncoder1D_kernel(const float* __restrict__ x,
                          const float* __restrict__ W1,
                          const float* __restrict__ b1,
                          const float* __restrict__ W2,
                          const float* __restrict__ b2,
                          float* __restrict__ out, int B) {
    extern __shared__ __align__(16) char dynsmem[];
    ull*  sws   = reinterpret_cast<ull*>(dynsmem);                   // packed weights
    char* wbase = dynsmem + SW_BYTES;

    // ---- cooperative weight fill (output-pair column-major layout) ----
    for (int i = threadIdx.x; i < NJ * JWU; i += blockDim.x) {
        int j = i >> 6, s = i & 63;
        float lo = 0.f, hi = 0.f;
        if (s < 28) {
            int k = s >> 2, p = s & 3;
            lo = W1[j * 49 + (2 * p) * 7 + k];
            if (p < 3) hi = W1[j * 49 + (2 * p + 1) * 7 + k];
        } else if (s < 32) {
            int p = s - 28;
            lo = b1[j * 7 + 2 * p];
            if (p < 3) hi = b1[j * 7 + 2 * p + 1];
        } else if (s < 60) {
            int k = (s - 32) >> 2, p = (s - 32) & 3;
            if (p < 3) {
                lo = W2[j * 42 + (2 * p) * 7 + k];
                hi = W2[j * 42 + (2 * p + 1) * 7 + k];
            }
        } else if (s < 63) {
            int p = s - 60;
            lo = b2[j * 6 + 2 * p];
            hi = b2[j * 6 + 2 * p + 1];
        }
        sws[i] = (ull)__float_as_uint(lo) | ((ull)__float_as_uint(hi) << 32);
    }
    __syncthreads();

    const int lane   = threadIdx.x & 31;
    const int warpId = threadIdx.x >> 5;
    const int warpBase = (blockIdx.x * WPB + warpId) * 64;
    if (warpBase >= B) return;

    char* wb = wbase + warpId * WARP_BYTES;
    ull*   xs   = reinterpret_cast<ull*>(wb);
    float* tile = reinterpret_cast<float*>(wb + XS_ULL * 8);

    // ---- stage x: coalesced LDG.128 -> tile region (row stride 25 floats) ----
    {
        const float4* xin = reinterpret_cast<const float4*>(x);
#pragma unroll
        for (int k = 0; k < 12; ++k) {
            int i = k * 32 + lane;               // [0,384): 64 rows x 6 float4
            int r = i / 6, c = i % 6;
            float4 v = make_float4(0.f, 0.f, 0.f, 0.f);
            if (warpBase + r < B) v = xin[(size_t)(warpBase + r) * 6 + c];
            float* d = tile + r * 25 + c * 4;
            d[0] = v.x; d[1] = v.y; d[2] = v.z; d[3] = v.w;
        }
    }
    __syncwarp();

    // ---- build packed-x in xs: xs[j*32+lane] = {x[e0][j], x[e1][j]} ----
#pragma unroll
    for (int j = 0; j < 24; ++j) {
        float a = tile[lane * 25 + j];
        float b = tile[(lane + 32) * 25 + j];
        xs[j * 32 + lane] = pack2(a, b);
    }
    __syncwarp();

    float* ta = tile + lane * TPAD;          // even float offset -> 8B aligned
    float* tb = tile + (lane + 32) * TPAD;

    ull fA[6], fB[6], fC[6];

#define XP(J) (xs[(J) * 32 + lane])
#define WP(J) (sws + (J) * JWU)
// features already packed per element: 3 bare STS.64 per row
#define ST(F, CB) do {                                                         \
        *reinterpret_cast<ull*>(ta + (CB))     = F[0];                         \
        *reinterpret_cast<ull*>(ta + (CB) + 2) = F[1];                         \
        *reinterpret_cast<ull*>(ta + (CB) + 4) = F[2];                         \
        *reinterpret_cast<ull*>(tb + (CB))     = F[3];                         \
        *reinterpret_cast<ull*>(tb + (CB) + 2) = F[4];                         \
        *reinterpret_cast<ull*>(tb + (CB) + 4) = F[5];                         \
    } while (0)

    // flush quarter tile: 64 rows x 36 cols -> out cols [G*36, G*36+36)
#define FLUSH(G) do {                                                          \
        __syncwarp();                                                          \
        _Pragma("unroll")                                                      \
        for (int k = 0; k < 18; ++k) {                                         \
            int i = k * 32 + lane;               /* [0,576): 64 rows x 9 f4 */ \
            int r = i / 9, c = i % 9;                                          \
            if (warpBase + r < B) {                                            \
                const float2* s = reinterpret_cast<const float2*>(             \
                    tile + r * TPAD + c * 4);                                  \
                float2 lo = s[0], hi = s[1];                                   \
                *reinterpret_cast<float4*>(                                    \
                    out + (size_t)(warpBase + r) * 144 + (G) * 36 + c * 4) =   \
                    make_float4(lo.x, lo.y, hi.x, hi.y);                       \
            }                                                                  \
        }                                                                      \
        __syncwarp();                                                          \
    } while (0)

    // ---- phase 0: joints {0..5}, local col = j*6 ----
    root_fwd (WP(0), XP(0),      fA);  ST(fA, 0 * 6);   // fA = f0
    joint_fwd(WP(1), XP(1), fA,  fB);  ST(fB, 1 * 6);   // fB = f1
    joint_fwd(WP(4), XP(4), fB,  fB);  ST(fB, 4 * 6);   // fB = f4
    joint_fwd(WP(2), XP(2), fA,  fC);  ST(fC, 2 * 6);   // fC = f2
    joint_fwd(WP(5), XP(5), fC,  fC);  ST(fC, 5 * 6);   // fC = f5
    joint_fwd(WP(3), XP(3), fA,  fA);  ST(fA, 3 * 6);   // fA = f3
    FLUSH(0);

    // ---- phase 1: joints {6..11}, local col = (j-6)*6  (fA=f3, fB=f4, fC=f5) ----
    joint_fwd(WP(6),  XP(6),  fA, fA); ST(fA, 0 * 6);   // fA = f6
    joint_fwd(WP(9),  XP(9),  fA, fA); ST(fA, 3 * 6);   // fA = f9
    joint_fwd(WP(7),  XP(7),  fB, fB); ST(fB, 1 * 6);   // fB = f7
    joint_fwd(WP(10), XP(10), fB, fB); ST(fB, 4 * 6);   // f10 (leaf)
    joint_fwd(WP(8),  XP(8),  fC, fC); ST(fC, 2 * 6);   // fC = f8
    joint_fwd(WP(11), XP(11), fC, fC); ST(fC, 5 * 6);   // f11 (leaf)
    FLUSH(1);

    // ---- phase 2: joints {12..17}, local col = (j-12)*6  (fA=f9) ----
    joint_fwd(WP(12), XP(12), fA, fB); ST(fB, 0 * 6);   // fB = f12
    joint_fwd(WP(15), XP(15), fB, fB); ST(fB, 3 * 6);   // f15 (leaf)
    joint_fwd(WP(13), XP(13), fA, fB); ST(fB, 1 * 6);   // fB = f13
    joint_fwd(WP(16), XP(16), fB, fB); ST(fB, 4 * 6);   // fB = f16 (keep)
    joint_fwd(WP(14), XP(14), fA, fC); ST(fC, 2 * 6);   // fC = f14
    joint_fwd(WP(17), XP(17), fC, fC); ST(fC, 5 * 6);   // fC = f17 (keep)
    FLUSH(2);

    // ---- phase 3: joints {18..23}, local col = (j-18)*6  (fB=f16, fC=f17) ----
    joint_fwd(WP(18), XP(18), fB, fB); ST(fB, 0 * 6);   // fB = f18
    joint_fwd(WP(20), XP(20), fB, fB); ST(fB, 2 * 6);   // fB = f20
    joint_fwd(WP(22), XP(22), fB, fB); ST(fB, 4 * 6);   // f22 (leaf)
    joint_fwd(WP(19), XP(19), fC, fC); ST(fC, 1 * 6);   // fC = f19
    joint_fwd(WP(21), XP(21), fC, fC); ST(fC, 3 * 6);   // fC = f21
    joint_fwd(WP(23), XP(23), fC, fC); ST(fC, 5 * 6);   // f23 (leaf)
    FLUSH(3);

#undef XP
#undef WP
#undef ST
#undef FLUSH
}

extern "C" void kernel_launch(void* const* d_in, const int* in_sizes, int n_in,
                              void* d_out, int out_size) {
    const float* x  = (const float*)d_in[0];
    const float* W1 = (const float*)d_in[1];
    const float* b1 = (const float*)d_in[2];
    const float* W2 = (const float*)d_in[3];
    const float* b2 = (const float*)d_in[4];
    float* out = (float*)d_out;

    int B = in_sizes[0] / 24;
    int warps  = (B + 63) / 64;
    int blocks = (warps + WPB - 1) / WPB;

    cudaFuncSetAttribute(StructureEncoder1D_kernel,
                         cudaFuncAttributeMaxDynamicSharedMemorySize, SMEM_BYTES);
    StructureEncoder1D_kernel<<<blocks, WPB * 32, SMEM_BYTES>>>(x, W1, b1, W2, b2, out, B);
}

// round 16
// speedup vs baseline: 1.9671x; 1.0089x over previous
#include <cuda_runtime.h>
#include <cstdint>

typedef unsigned long long ull;

// ---------- packed f32x2 helpers (sm_103a) ----------
__device__ __forceinline__ ull pack2(float a, float b) {
    ull r; asm("mov.b64 %0, {%1, %2};" : "=l"(r) : "f"(a), "f"(b)); return r;
}
__device__ __forceinline__ void unpack2(ull v, float& a, float& b) {
    asm("mov.b64 {%0, %1}, %2;" : "=f"(a), "=f"(b) : "l"(v));
}
__device__ __forceinline__ ull ffma2(ull a, ull b, ull c) {
    ull d; asm("fma.rn.f32x2 %0, %1, %2, %3;" : "=l"(d) : "l"(a), "l"(b), "l"(c)); return d;
}
__device__ __forceinline__ ull relu2(ull v) {
    float a, b; unpack2(v, a, b);
    return pack2(fmaxf(a, 0.f), fmaxf(b, 0.f));
}
#define DUP(f) pack2((f), (f))

#define NJ 24
#define JWU 64          // ull per joint (col-major output-pair layout, padded)
#define WPB 14          // warps per block (448 thr -> reg cap 146)
#define XPAD 25         // x slab row stride in floats (odd -> conflict-free scalar LDS)
#define TPAD 36         // quarter-tile row stride (16B-aligned rows; 18l mod 32 distinct/phase)
#define XSLAB_BYTES (64 * XPAD * 4)              // 6400
#define TILE_FLOATS (64 * TPAD)                  // 9216 B
#define SW_BYTES (NJ * JWU * 8)                  // 12288
#define WARP_BYTES (XSLAB_BYTES + TILE_FLOATS * 4)         // 15616
#define SMEM_BYTES (SW_BYTES + WPB * WARP_BYTES)           // 230912 <= 232448

// Weight image per joint (ull index s in [0,64)):
//  s in [0,28):  layer1 W-pairs: s = k*4+p, pair = (W1[2p][k], W1[2p+1][k]); p=3 -> (W1[6][k], 0)
//  s in [28,32): layer1 bias pairs: (b1[2p], b1[2p+1]); p=3 -> (b1[6], 0)
//  s in [32,60): layer2 W-pairs: s-32 = k*4+p (p<3), pair = (W2[2p][k], W2[2p+1][k]); p=3 pad
//  s in [60,63): layer2 bias pairs: (b2[2p], b2[2p+1]);  s=63 pad

// ---- joint forward: both batch elements (A, B) share weight regs.
// pf[0..2] = elem-A packed trio (f0,f1)(f2,f3)(f4,f5), pf[3..5] = elem-B. fo same layout.
__device__ __forceinline__ void joint_fwd(const ull* jw, float xa, float xb,
                                          const ull* pf, ull* fo) {
    ull dA[7], dB[7];
    dA[0] = DUP(xa); dB[0] = DUP(xb);
#pragma unroll
    for (int s = 0; s < 3; ++s) {
        float a, b, c, d;
        unpack2(pf[s],     a, b);
        unpack2(pf[3 + s], c, d);
        dA[1 + 2*s] = DUP(a); dA[2 + 2*s] = DUP(b);
        dB[1 + 2*s] = DUP(c); dB[2 + 2*s] = DUP(d);
    }
    const ulonglong2* W = reinterpret_cast<const ulonglong2*>(jw);
    ulonglong2 b01 = W[14], b23 = W[15];
    ull aA0 = b01.x, aA1 = b01.y, aA2 = b23.x, aA3 = b23.y;
    ull aB0 = b01.x, aB1 = b01.y, aB2 = b23.x, aB3 = b23.y;
#pragma unroll
    for (int k = 0; k < 7; ++k) {
        ulonglong2 w01 = W[k * 2], w23 = W[k * 2 + 1];
        aA0 = ffma2(w01.x, dA[k], aA0);  aB0 = ffma2(w01.x, dB[k], aB0);
        aA1 = ffma2(w01.y, dA[k], aA1);  aB1 = ffma2(w01.y, dB[k], aB1);
        aA2 = ffma2(w23.x, dA[k], aA2);  aB2 = ffma2(w23.x, dB[k], aB2);
        aA3 = ffma2(w23.y, dA[k], aA3);  aB3 = ffma2(w23.y, dB[k], aB3);
    }
    aA0 = relu2(aA0); aA1 = relu2(aA1); aA2 = relu2(aA2); aA3 = relu2(aA3);
    aB0 = relu2(aB0); aB1 = relu2(aB1); aB2 = relu2(aB2); aB3 = relu2(aB3);

    ull eA[7], eB[7];
    {
        float a, b;
        unpack2(aA0, a, b); eA[0] = DUP(a); eA[1] = DUP(b);
        unpack2(aA1, a, b); eA[2] = DUP(a); eA[3] = DUP(b);
        unpack2(aA2, a, b); eA[4] = DUP(a); eA[5] = DUP(b);
        unpack2(aA3, a, b); eA[6] = DUP(a);
        unpack2(aB0, a, b); eB[0] = DUP(a); eB[1] = DUP(b);
        unpack2(aB1, a, b); eB[2] = DUP(a); eB[3] = DUP(b);
        unpack2(aB2, a, b); eB[4] = DUP(a); eB[5] = DUP(b);
        unpack2(aB3, a, b); eB[6] = DUP(a);
    }
    ulonglong2 c01 = *reinterpret_cast<const ulonglong2*>(jw + 60);
    ull c2 = jw[62];
    ull gA0 = c01.x, gA1 = c01.y, gA2 = c2;
    ull gB0 = c01.x, gB1 = c01.y, gB2 = c2;
#pragma unroll
    for (int k = 0; k < 7; ++k) {
        const ulonglong2* L = reinterpret_cast<const ulonglong2*>(jw + 32 + k * 4);
        ulonglong2 w01 = L[0], w2p = L[1];
        gA0 = ffma2(w01.x, eA[k], gA0);  gB0 = ffma2(w01.x, eB[k], gB0);
        gA1 = ffma2(w01.y, eA[k], gA1);  gB1 = ffma2(w01.y, eB[k], gB1);
        gA2 = ffma2(w2p.x, eA[k], gA2);  gB2 = ffma2(w2p.x, eB[k], gB2);
    }
    fo[0] = relu2(gA0); fo[1] = relu2(gA1); fo[2] = relu2(gA2);
    fo[3] = relu2(gB0); fo[4] = relu2(gB1); fo[5] = relu2(gB2);
}

// root: parent features are zero -> layer1 keeps only the x term + bias
__device__ __forceinline__ void root_fwd(const ull* jw, float xa, float xb, ull* fo) {
    ull dA = DUP(xa), dB = DUP(xb);
    const ulonglong2* W = reinterpret_cast<const ulonglong2*>(jw);
    ulonglong2 w01 = W[0], w23 = W[1], b01 = W[14], b23 = W[15];
    ull aA0 = ffma2(w01.x, dA, b01.x), aB0 = ffma2(w01.x, dB, b01.x);
    ull aA1 = ffma2(w01.y, dA, b01.y), aB1 = ffma2(w01.y, dB, b01.y);
    ull aA2 = ffma2(w23.x, dA, b23.x), aB2 = ffma2(w23.x, dB, b23.x);
    ull aA3 = ffma2(w23.y, dA, b23.y), aB3 = ffma2(w23.y, dB, b23.y);
    aA0 = relu2(aA0); aA1 = relu2(aA1); aA2 = relu2(aA2); aA3 = relu2(aA3);
    aB0 = relu2(aB0); aB1 = relu2(aB1); aB2 = relu2(aB2); aB3 = relu2(aB3);

    ull eA[7], eB[7];
    {
        float a, b;
        unpack2(aA0, a, b); eA[0] = DUP(a); eA[1] = DUP(b);
        unpack2(aA1, a, b); eA[2] = DUP(a); eA[3] = DUP(b);
        unpack2(aA2, a, b); eA[4] = DUP(a); eA[5] = DUP(b);
        unpack2(aA3, a, b); eA[6] = DUP(a);
        unpack2(aB0, a, b); eB[0] = DUP(a); eB[1] = DUP(b);
        unpack2(aB1, a, b); eB[2] = DUP(a); eB[3] = DUP(b);
        unpack2(aB2, a, b); eB[4] = DUP(a); eB[5] = DUP(b);
        unpack2(aB3, a, b); eB[6] = DUP(a);
    }
    ulonglong2 c01 = *reinterpret_cast<const ulonglong2*>(jw + 60);
    ull c2 = jw[62];
    ull gA0 = c01.x, gA1 = c01.y, gA2 = c2;
    ull gB0 = c01.x, gB1 = c01.y, gB2 = c2;
#pragma unroll
    for (int k = 0; k < 7; ++k) {
        const ulonglong2* L = reinterpret_cast<const ulonglong2*>(jw + 32 + k * 4);
        ulonglong2 w01 = L[0], w2p = L[1];
        gA0 = ffma2(w01.x, eA[k], gA0);  gB0 = ffma2(w01.x, eB[k], gB0);
        gA1 = ffma2(w01.y, eA[k], gA1);  gB1 = ffma2(w01.y, eB[k], gB1);
        gA2 = ffma2(w2p.x, eA[k], gA2);  gB2 = ffma2(w2p.x, eB[k], gB2);
    }
    fo[0] = relu2(gA0); fo[1] = relu2(gA1); fo[2] = relu2(gA2);
    fo[3] = relu2(gB0); fo[4] = relu2(gB1); fo[5] = relu2(gB2);
}

__global__ void __launch_bounds__(WPB * 32)
StructureEncoder1D_kernel(const float* __restrict__ x,
                          const float* __restrict__ W1,
                          const float* __restrict__ b1,
                          const float* __restrict__ W2,
                          const float* __restrict__ b2,
                          float* __restrict__ out, int B) {
    extern __shared__ __align__(16) char dynsmem[];
    ull*  sws   = reinterpret_cast<ull*>(dynsmem);                   // packed weights
    char* wbase = dynsmem + SW_BYTES;

    // ---- cooperative weight fill (output-pair column-major layout) ----
    for (int i = threadIdx.x; i < NJ * JWU; i += blockDim.x) {
        int j = i >> 6, s = i & 63;
        float lo = 0.f, hi = 0.f;
        if (s < 28) {
            int k = s >> 2, p = s & 3;
            lo = W1[j * 49 + (2 * p) * 7 + k];
            if (p < 3) hi = W1[j * 49 + (2 * p + 1) * 7 + k];
        } else if (s < 32) {
            int p = s - 28;
            lo = b1[j * 7 + 2 * p];
            if (p < 3) hi = b1[j * 7 + 2 * p + 1];
        } else if (s < 60) {
            int k = (s - 32) >> 2, p = (s - 32) & 3;
            if (p < 3) {
                lo = W2[j * 42 + (2 * p) * 7 + k];
                hi = W2[j * 42 + (2 * p + 1) * 7 + k];
            }
        } else if (s < 63) {
            int p = s - 60;
            lo = b2[j * 6 + 2 * p];
            hi = b2[j * 6 + 2 * p + 1];
        }
        sws[i] = (ull)__float_as_uint(lo) | ((ull)__float_as_uint(hi) << 32);
    }
    __syncthreads();

    const int lane   = threadIdx.x & 31;
    const int warpId = threadIdx.x >> 5;
    const int warpBase = (blockIdx.x * WPB + warpId) * 64;
    if (warpBase >= B) return;

    char* wb = wbase + warpId * WARP_BYTES;
    float* xslab = reinterpret_cast<float*>(wb);                 // persistent x
    float* tile  = reinterpret_cast<float*>(wb + XSLAB_BYTES);   // output tile

    // ---- stage x: coalesced LDG.128 -> xslab (row stride 25 floats) ----
    {
        const float4* xin = reinterpret_cast<const float4*>(x);
#pragma unroll
        for (int k = 0; k < 12; ++k) {
            int i = k * 32 + lane;               // [0,384): 64 rows x 6 float4
            int r = i / 6, c = i % 6;
            float4 v = make_float4(0.f, 0.f, 0.f, 0.f);
            if (warpBase + r < B) v = xin[(size_t)(warpBase + r) * 6 + c];
            float* d = xslab + r * XPAD + c * 4;
            d[0] = v.x; d[1] = v.y; d[2] = v.z; d[3] = v.w;
        }
    }
    __syncwarp();

    float* ta = tile + lane * TPAD;          // 144B row offset -> 16B aligned
    float* tb = tile + (lane + 32) * TPAD;

    ull fA[6], fB[6], fC[6];

#define XA(J) (xslab[lane * XPAD + (J)])
#define XB(J) (xslab[(lane + 32) * XPAD + (J)])
#define WP(J) (sws + (J) * JWU)
// features already packed per element: 3 bare STS.64 per row
#define ST(F, CB) do {                                                         \
        *reinterpret_cast<ull*>(ta + (CB))     = F[0];                         \
        *reinterpret_cast<ull*>(ta + (CB) + 2) = F[1];                         \
        *reinterpret_cast<ull*>(ta + (CB) + 4) = F[2];                         \
        *reinterpret_cast<ull*>(tb + (CB))     = F[3];                         \
        *reinterpret_cast<ull*>(tb + (CB) + 2) = F[4];                         \
        *reinterpret_cast<ull*>(tb + (CB) + 4) = F[5];                         \
    } while (0)

    // flush quarter tile: 64 rows x 36 cols -> out cols [G*36, G*36+36)
    // rows are 16B aligned (TPAD % 4 == 0) -> single LDS.128 per piece
#define FLUSH(G) do {                                                          \
        __syncwarp();                                                          \
        _Pragma("unroll")                                                      \
        for (int k = 0; k < 18; ++k) {                                         \
            int i = k * 32 + lane;               /* [0,576): 64 rows x 9 f4 */ \
            int r = i / 9, c = i % 9;                                          \
            if (warpBase + r < B) {                                            \
                float4 v = *reinterpret_cast<const float4*>(                   \
                    tile + r * TPAD + c * 4);                                  \
                *reinterpret_cast<float4*>(                                    \
                    out + (size_t)(warpBase + r) * 144 + (G) * 36 + c * 4) = v;\
            }                                                                  \
        }                                                                      \
        __syncwarp();                                                          \
    } while (0)

    // ---- phase 0: joints {0..5}, local col = j*6 ----
    root_fwd (WP(0), XA(0), XB(0),      fA);  ST(fA, 0 * 6);   // fA = f0
    joint_fwd(WP(1), XA(1), XB(1), fA,  fB);  ST(fB, 1 * 6);   // fB = f1
    joint_fwd(WP(4), XA(4), XB(4), fB,  fB);  ST(fB, 4 * 6);   // fB = f4
    joint_fwd(WP(2), XA(2), XB(2), fA,  fC);  ST(fC, 2 * 6);   // fC = f2
    joint_fwd(WP(5), XA(5), XB(5), fC,  fC);  ST(fC, 5 * 6);   // fC = f5
    joint_fwd(WP(3), XA(3), XB(3), fA,  fA);  ST(fA, 3 * 6);   // fA = f3
    FLUSH(0);

    // ---- phase 1: joints {6..11}, local col = (j-6)*6  (fA=f3, fB=f4, fC=f5) ----
    joint_fwd(WP(6),  XA(6),  XB(6),  fA, fA); ST(fA, 0 * 6);  // fA = f6
    joint_fwd(WP(9),  XA(9),  XB(9),  fA, fA); ST(fA, 3 * 6);  // fA = f9
    joint_fwd(WP(7),  XA(7),  XB(7),  fB, fB); ST(fB, 1 * 6);  // fB = f7
    joint_fwd(WP(10), XA(10), XB(10), fB, fB); ST(fB, 4 * 6);  // f10 (leaf)
    joint_fwd(WP(8),  XA(8),  XB(8),  fC, fC); ST(fC, 2 * 6);  // fC = f8
    joint_fwd(WP(11), XA(11), XB(11), fC, fC); ST(fC, 5 * 6);  // f11 (leaf)
    FLUSH(1);

    // ---- phase 2: joints {12..17}, local col = (j-12)*6  (fA=f9) ----
    joint_fwd(WP(12), XA(12), XB(12), fA, fB); ST(fB, 0 * 6);  // fB = f12
    joint_fwd(WP(15), XA(15), XB(15), fB, fB); ST(fB, 3 * 6);  // f15 (leaf)
    joint_fwd(WP(13), XA(13), XB(13), fA, fB); ST(fB, 1 * 6);  // fB = f13
    joint_fwd(WP(16), XA(16), XB(16), fB, fB); ST(fB, 4 * 6);  // fB = f16 (keep)
    joint_fwd(WP(14), XA(14), XB(14), fA, fC); ST(fC, 2 * 6);  // fC = f14
    joint_fwd(WP(17), XA(17), XB(17), fC, fC); ST(fC, 5 * 6);  // fC = f17 (keep)
    FLUSH(2);

    // ---- phase 3: joints {18..23}, local col = (j-18)*6  (fB=f16, fC=f17) ----
    joint_fwd(WP(18), XA(18), XB(18), fB, fB); ST(fB, 0 * 6);  // fB = f18
    joint_fwd(WP(20), XA(20), XB(20), fB, fB); ST(fB, 2 * 6);  // fB = f20
    joint_fwd(WP(22), XA(22), XB(22), fB, fB); ST(fB, 4 * 6);  // f22 (leaf)
    joint_fwd(WP(19), XA(19), XB(19), fC, fC); ST(fC, 1 * 6);  // fC = f19
    joint_fwd(WP(21), XA(21), XB(21), fC, fC); ST(fC, 3 * 6);  // fC = f21
    joint_fwd(WP(23), XA(23), XB(23), fC, fC); ST(fC, 5 * 6);  // f23 (leaf)
    FLUSH(3);

#undef XA
#undef XB
#undef WP
#undef ST
#undef FLUSH
}

extern "C" void kernel_launch(void* const* d_in, const int* in_sizes, int n_in,
                              void* d_out, int out_size) {
    const float* x  = (const float*)d_in[0];
    const float* W1 = (const float*)d_in[1];
    const float* b1 = (const float*)d_in[2];
    const float* W2 = (const float*)d_in[3];
    const float* b2 = (const float*)d_in[4];
    float* out = (float*)d_out;

    int B = in_sizes[0] / 24;
    int warps  = (B + 63) / 64;
    int blocks = (warps + WPB - 1) / WPB;

    cudaFuncSetAttribute(StructureEncoder1D_kernel,
                         cudaFuncAttributeMaxDynamicSharedMemorySize, SMEM_BYTES);
    StructureEncoder1D_kernel<<<blocks, WPB * 32, SMEM_BYTES>>>(x, W1, b1, W2, b2, out, B);
}